// round 15
// baseline (speedup 1.0000x reference)
#include <cuda_runtime.h>
#include <cuda_fp16.h>

#define Nn 100000
#define Ee 1200000
#define Dd 64
#define NGIN 4
#define NPRED 5
#define NG 512

// SW128 swizzle on byte offsets (bits [6:4] ^= bits [9:7])
#define SW(b) ((b) ^ (((b) >> 3) & 0x70))

__device__ __forceinline__ unsigned sptr(const void* p){
    return (unsigned)__cvta_generic_to_shared(p);
}
__device__ __forceinline__ void ldm_x4(unsigned addr, unsigned &r0, unsigned &r1,
                                       unsigned &r2, unsigned &r3){
    asm volatile("ldmatrix.sync.aligned.m8n8.x4.shared.b16 {%0,%1,%2,%3}, [%4];"
        : "=r"(r0),"=r"(r1),"=r"(r2),"=r"(r3) : "r"(addr));
}
__device__ __forceinline__ void ldm_x4t(unsigned addr, unsigned &r0, unsigned &r1,
                                        unsigned &r2, unsigned &r3){
    asm volatile("ldmatrix.sync.aligned.m8n8.x4.trans.shared.b16 {%0,%1,%2,%3}, [%4];"
        : "=r"(r0),"=r"(r1),"=r"(r2),"=r"(r3) : "r"(addr));
}
__device__ __forceinline__ void mma16816(float* d, const unsigned* a, unsigned b0, unsigned b1){
    asm volatile("mma.sync.aligned.m16n8k16.row.col.f32.f16.f16.f32 "
        "{%0,%1,%2,%3}, {%4,%5,%6,%7}, {%8,%9}, {%0,%1,%2,%3};"
        : "+f"(d[0]),"+f"(d[1]),"+f"(d[2]),"+f"(d[3])
        : "r"(a[0]),"r"(a[1]),"r"(a[2]),"r"(a[3]),"r"(b0),"r"(b1));
}

// ---------------- scratch ----------------
__device__ uint2 g_h16[Nn*16];      // input h as half2 (gather source, layer 0): 128 B/row
__device__ uint4 g_pre16[Nn*8];     // agg output, fp16 (GEMM1 input): 128 B/row
__device__ uint4 g_t16[Nn*8];       // GEMM1 output, fp16 (GEMM2 input, pre-BN)
__device__ uint4 g_u16[Nn*8];       // GEMM2 output, fp16 (gather source next layer / final pool)
__device__ int   g_deg[Nn];
__device__ int   g_rowptr[Nn+1];
__device__ int   g_rank[Ee];        // within-destination rank of each edge
__device__ int   g_col[Ee];         // pre-scaled: src*16 (uint2 row offset)
__device__ int   g_bsum[128];
__device__ int   g_scanCount;       // scan/scatter barrier counter (reset in k_hist)
__device__ int   g_poolCount;       // pool/score barrier counter (reset in k_hist)
__device__ float g_stats[8*128];    // 8 slots: [0:64) sum, [64:128) sumsq
__device__ float g_pooled[NPRED*NG*Dd];

// ---------------- CSR hist + rank + h->fp16 conversion + zeroing ----------------
__global__ void k_hist(const int* __restrict__ dst, const float* __restrict__ h){
    int i = blockIdx.x*blockDim.x + threadIdx.x;
    int nthr = gridDim.x*blockDim.x;
    if (i < Ee){
        int r = atomicAdd(&g_deg[dst[i]], 1);
        g_rank[i] = r;
    }
    const float4* h4 = (const float4*)h;
    for (int j = i; j < Nn*16; j += nthr){
        float4 x = h4[j];
        __half2 p0 = __float22half2_rn(make_float2(x.x, x.y));
        __half2 p1 = __float22half2_rn(make_float2(x.z, x.w));
        uint2 o;
        o.x = *(unsigned*)&p0;
        o.y = *(unsigned*)&p1;
        g_h16[j] = o;
    }
    if (i < NPRED*NG*Dd) g_pooled[i] = 0.f;
    if (i < 8*128) g_stats[i] = 0.f;
    if (i == 0){ g_scanCount = 0; g_poolCount = 0; }
}

// fused scan + scatter: phase1 local scan + bsum, barrier, phase2 prefix + rowptr,
// barrier, phase3 grid-strided atomic-free scatter. 98 resident blocks.
__global__ void k_scanscatter(const int* __restrict__ src, const int* __restrict__ dst, int nb){
    __shared__ int s[1024];
    __shared__ int sb[128];
    int b = blockIdx.x;
    int i = b*1024 + threadIdx.x;
    int v = 0;
    if (i < Nn){ v = g_deg[i]; g_deg[i] = 0; }   // self-clean for next replay
    s[threadIdx.x] = v;
    __syncthreads();
    #pragma unroll
    for (int off = 1; off < 1024; off <<= 1){
        int x = (threadIdx.x >= off) ? s[threadIdx.x - off] : 0;
        __syncthreads();
        s[threadIdx.x] += x;
        __syncthreads();
    }
    if (threadIdx.x == 1023){
        g_bsum[b] = s[1023];
    }
    __syncthreads();
    if (threadIdx.x == 0){
        __threadfence();
        atomicAdd(&g_scanCount, 1);
        while (atomicAdd(&g_scanCount, 0) < nb) { }
        __threadfence();
    }
    __syncthreads();

    if (threadIdx.x < 128) sb[threadIdx.x] = (threadIdx.x < nb) ? g_bsum[threadIdx.x] : 0;
    __syncthreads();
    #pragma unroll
    for (int off = 1; off < 128; off <<= 1){
        int x = 0;
        if (threadIdx.x < 128 && threadIdx.x >= off) x = sb[threadIdx.x - off];
        __syncthreads();
        if (threadIdx.x < 128) sb[threadIdx.x] += x;
        __syncthreads();
    }
    int excl = (b > 0) ? sb[b-1] : 0;
    if (i < Nn) g_rowptr[i+1] = s[threadIdx.x] + excl;
    if (i == 0) g_rowptr[0] = 0;
    __syncthreads();
    if (threadIdx.x == 0){
        __threadfence();
        atomicAdd(&g_scanCount, 1);
        while (atomicAdd(&g_scanCount, 0) < 2*nb) { }
        __threadfence();
    }
    __syncthreads();

    int nthr = nb*1024;
    for (int e = i; e < Ee; e += nthr){
        int p = g_rowptr[dst[e]] + g_rank[e];
        g_col[p] = src[e] * 16;      // pre-scaled uint2 row offset
    }
}

// ---------------- per-block BN coefficient computation ----------------
__device__ __forceinline__ void bn_coeffs(const float* __restrict__ stats,
                                          const float* __restrict__ gamma,
                                          const float* __restrict__ beta,
                                          float* sA, float* sB, int tid)
{
    if (tid < 64){
        float m = stats[tid]    * (1.f/Nn);
        float v = stats[64+tid] * (1.f/Nn) - m*m;
        float a = gamma[tid] * rsqrtf(v + 1e-5f);
        sA[tid] = a;
        sB[tid] = beta[tid] - m*a;
    }
}

// ---------------- aggregation: TWO nodes per warp (16 lanes x 4 halfs each),
// fp16 gather, pipelined col prefetch, half2 BN+relu, fused pooling (R13 proven) ----------------
template<int MODE>
__global__ void __launch_bounds__(256) k_agg(const uint2* __restrict__ hh,
                                             const float* __restrict__ eps, int layer,
                                             const int* __restrict__ gid,
                                             float* __restrict__ pooled,
                                             const float* __restrict__ statsIn,
                                             const float* __restrict__ gamma,
                                             const float* __restrict__ beta)
{
    __shared__ float sA[64], sB[64];
    __shared__ float sPool[16][64];
    __shared__ int   sGid[16];
    int tid  = threadIdx.x;
    int wp   = tid >> 5;
    int lane = tid & 31;
    int half = lane >> 4;
    int hl   = lane & 15;
    int nl   = wp*2 + half;              // 0..15 node within block
    int w    = blockIdx.x*16 + nl;       // Nn % 16 == 0 -> always valid

    if (MODE){
        bn_coeffs(statsIn, gamma, beta, sA, sB, tid);
        __syncthreads();
    }

    int c0 = hl*4;
    __half2 A0 = __float2half2_rn(1.f), A1 = A0;
    __half2 B0 = __float2half2_rn(0.f), B1 = B0;
    const __half2 Z2 = __float2half2_rn(0.f);
    if (MODE){
        A0 = __floats2half2_rn(sA[c0],   sA[c0+1]);
        A1 = __floats2half2_rn(sA[c0+2], sA[c0+3]);
        B0 = __floats2half2_rn(sB[c0],   sB[c0+1]);
        B1 = __floats2half2_rn(sB[c0+2], sB[c0+3]);
    }
    float epv = 1.f + eps[layer];

    uint2 sv = hh[w*16 + hl];
    __half2 s0 = *(__half2*)&sv.x, s1 = *(__half2*)&sv.y;
    if (MODE){
        s0 = __hmax2(__hfma2(s0, A0, B0), Z2);
        s1 = __hmax2(__hfma2(s1, A1, B1), Z2);
    }
    float2 f0 = __half22float2(s0), f1 = __half22float2(s1);
    *(float2*)&sPool[nl][c0]     = f0;
    *(float2*)&sPool[nl][c0 + 2] = f1;
    if (hl == 0) sGid[nl] = gid[w];

    float ax0 = f0.x*epv, ax1 = f0.y*epv, ax2 = f1.x*epv, ax3 = f1.y*epv;
    int e = g_rowptr[w], end = g_rowptr[w+1];

    int o0=0, o1=0, o2=0, o3=0;
    bool have = (e + 4 <= end);
    if (have){ o0 = g_col[e]; o1 = g_col[e+1]; o2 = g_col[e+2]; o3 = g_col[e+3]; }
    while (have){
        int p0=0, p1=0, p2=0, p3=0;
        bool nxt = (e + 8 <= end);
        if (nxt){ p0 = g_col[e+4]; p1 = g_col[e+5]; p2 = g_col[e+6]; p3 = g_col[e+7]; }
        uint2 v0 = hh[o0+hl], v1 = hh[o1+hl], v2 = hh[o2+hl], v3 = hh[o3+hl];
        __half2 a0 = *(__half2*)&v0.x, b0 = *(__half2*)&v0.y;
        __half2 a1 = *(__half2*)&v1.x, b1 = *(__half2*)&v1.y;
        __half2 a2 = *(__half2*)&v2.x, b2 = *(__half2*)&v2.y;
        __half2 a3 = *(__half2*)&v3.x, b3 = *(__half2*)&v3.y;
        if (MODE){
            a0 = __hmax2(__hfma2(a0,A0,B0),Z2); b0 = __hmax2(__hfma2(b0,A1,B1),Z2);
            a1 = __hmax2(__hfma2(a1,A0,B0),Z2); b1 = __hmax2(__hfma2(b1,A1,B1),Z2);
            a2 = __hmax2(__hfma2(a2,A0,B0),Z2); b2 = __hmax2(__hfma2(b2,A1,B1),Z2);
            a3 = __hmax2(__hfma2(a3,A0,B0),Z2); b3 = __hmax2(__hfma2(b3,A1,B1),Z2);
        }
        float2 g0 = __half22float2(a0), h0 = __half22float2(b0);
        float2 g1 = __half22float2(a1), h1 = __half22float2(b1);
        float2 g2 = __half22float2(a2), h2 = __half22float2(b2);
        float2 g3 = __half22float2(a3), h3 = __half22float2(b3);
        ax0 += (g0.x + g1.x) + (g2.x + g3.x);
        ax1 += (g0.y + g1.y) + (g2.y + g3.y);
        ax2 += (h0.x + h1.x) + (h2.x + h3.x);
        ax3 += (h0.y + h1.y) + (h2.y + h3.y);
        o0 = p0; o1 = p1; o2 = p2; o3 = p3;
        e += 4;
        have = nxt;
    }
    for (; e < end; e++){
        uint2 v = hh[g_col[e] + hl];
        __half2 a = *(__half2*)&v.x, b = *(__half2*)&v.y;
        if (MODE){
            a = __hmax2(__hfma2(a,A0,B0),Z2);
            b = __hmax2(__hfma2(b,A1,B1),Z2);
        }
        float2 g = __half22float2(a), hq = __half22float2(b);
        ax0 += g.x; ax1 += g.y; ax2 += hq.x; ax3 += hq.y;
    }

    __half2 r0 = __floats2half2_rn(ax0, ax1);
    __half2 r1 = __floats2half2_rn(ax2, ax3);
    uint2 ov; ov.x = *(unsigned*)&r0; ov.y = *(unsigned*)&r1;
    ((uint2*)g_pre16)[w*16 + hl] = ov;

    __syncthreads();
    if (tid < 64){
        float acc = sPool[0][tid];
        int cur = sGid[0];
        #pragma unroll
        for (int r = 1; r < 16; r++){
            int g = sGid[r];
            if (g != cur){
                atomicAdd(&pooled[cur*64 + tid], acc);
                cur = g; acc = sPool[r][tid];
            } else {
                acc += sPool[r][tid];
            }
        }
        atomicAdd(&pooled[cur*64 + tid], acc);
    }
}

// ---------------- persistent HMMA GEMM: grid=296, tile loop; fp16 in/out, fp32 acc,
// fused BN-stats (smem-accumulated across tiles); optional fused BN+relu on INPUT ----------------
template<int APPLY>
__global__ void __launch_bounds__(256, 2) k_gemm(const uint4* __restrict__ X16,
                                                 const float* __restrict__ W,
                                                 const float* __restrict__ bias,
                                                 unsigned* __restrict__ Y,   // half2 units
                                                 const float* __restrict__ statsIn,
                                                 float* __restrict__ statsOut,
                                                 const float* __restrict__ gamma,
                                                 const float* __restrict__ beta)
{
    __shared__ uint4 sX4[256*8];
    __shared__ uint4 sW4[64*8];
    __shared__ float sA[64], sB[64], sBias[64];
    __shared__ float sSum[64], sSsq[64];
    char* sX  = (char*)sX4;
    char* sWt = (char*)sW4;
    int tid = threadIdx.x;
    if (tid < 64){ sSum[tid] = 0.f; sSsq[tid] = 0.f; sBias[tid] = bias[tid]; }
    if (APPLY) bn_coeffs(statsIn, gamma, beta, sA, sB, tid);

    {
        const float2* W2 = (const float2*)W;
        #pragma unroll
        for (int it = 0; it < 8; it++){
            int idx = tid + it*256;
            int k  = idx >> 5;
            int n2 = idx & 31;
            __half2 hw = __float22half2_rn(W2[idx]);
            *(unsigned*)(sWt + SW(k*128 + n2*4)) = *(unsigned*)&hw;
        }
    }
    __syncthreads();

    int wid  = tid >> 5;
    int lane = tid & 31;
    int warpRow = wid * 32;
    unsigned sXb = sptr(sX);
    unsigned sWb = sptr(sWt);
    int sel = lane >> 3;
    int lr  = lane & 7;
    int g   = lane >> 2;
    int i4  = lane & 3;
    int i2  = i4 * 2;

    for (int rowBase = blockIdx.x*256; rowBase < Nn; rowBase += gridDim.x*256){
        // load X tile (fp16 global) -> swizzled smem, optional BN+relu
        #pragma unroll
        for (int it = 0; it < 8; it++){
            int idx = tid + it*256;
            int r = idx >> 3;
            int c = idx & 7;
            int gr = rowBase + r;
            uint4 v = make_uint4(0,0,0,0);
            if (gr < Nn){
                v = X16[gr*8 + c];
                if (APPLY){
                    __half2* ph = (__half2*)&v;
                    #pragma unroll
                    for (int q = 0; q < 4; q++){
                        float2 f = __half22float2(ph[q]);
                        int col = c*8 + q*2;
                        f.x = fmaxf(fmaf(f.x, sA[col],   sB[col]),   0.f);
                        f.y = fmaxf(fmaf(f.y, sA[col+1], sB[col+1]), 0.f);
                        ph[q] = __float22half2_rn(f);
                    }
                }
            }
            *(uint4*)(sX + SW(r*128 + c*16)) = v;
        }
        __syncthreads();

        float acc[2][8][4];
        #pragma unroll
        for (int mt = 0; mt < 2; mt++)
            #pragma unroll
            for (int nt = 0; nt < 8; nt++)
                #pragma unroll
                for (int q = 0; q < 4; q++) acc[mt][nt][q] = 0.f;

        #pragma unroll
        for (int ks = 0; ks < 4; ks++){
            unsigned a[2][4];
            #pragma unroll
            for (int mt = 0; mt < 2; mt++){
                int rowl = warpRow + mt*16 + lr + ((sel & 1) << 3);
                int kb   = ks*32 + ((sel >> 1) << 4);
                ldm_x4(sXb + SW(rowl*128 + kb), a[mt][0], a[mt][1], a[mt][2], a[mt][3]);
            }
            #pragma unroll
            for (int j = 0; j < 4; j++){
                int kr = ks*16 + lr + ((sel & 1) << 3);
                int nb = j*32 + ((sel >> 1) << 4);
                unsigned b0, b1, b2, b3;
                ldm_x4t(sWb + SW(kr*128 + nb), b0, b1, b2, b3);
                mma16816(acc[0][2*j],   a[0], b0, b1);
                mma16816(acc[1][2*j],   a[1], b0, b1);
                mma16816(acc[0][2*j+1], a[0], b2, b3);
                mma16816(acc[1][2*j+1], a[1], b2, b3);
            }
        }

        // epilogue: bias, fp16 store, BN-stats (shuffle reduce -> smem atomics)
        #pragma unroll
        for (int nt = 0; nt < 8; nt++){
            float b0f = sBias[nt*8 + i2];
            float b1f = sBias[nt*8 + i2 + 1];
            float s0 = 0.f, s1 = 0.f, q0 = 0.f, q1 = 0.f;
            #pragma unroll
            for (int mt = 0; mt < 2; mt++){
                int row0 = rowBase + warpRow + mt*16 + g;
                float d0 = acc[mt][nt][0] + b0f;
                float d1 = acc[mt][nt][1] + b1f;
                float d2 = acc[mt][nt][2] + b0f;
                float d3 = acc[mt][nt][3] + b1f;
                if (row0 < Nn){
                    __half2 hv = __float22half2_rn(make_float2(d0, d1));
                    Y[row0*32 + nt*4 + i4] = *(unsigned*)&hv;
                    s0 += d0; s1 += d1; q0 += d0*d0; q1 += d1*d1;
                }
                if (row0 + 8 < Nn){
                    __half2 hv = __float22half2_rn(make_float2(d2, d3));
                    Y[(row0+8)*32 + nt*4 + i4] = *(unsigned*)&hv;
                    s0 += d2; s1 += d3; q0 += d2*d2; q1 += d3*d3;
                }
            }
            #pragma unroll
            for (int off = 4; off < 32; off <<= 1){
                s0 += __shfl_xor_sync(0xffffffffu, s0, off);
                s1 += __shfl_xor_sync(0xffffffffu, s1, off);
                q0 += __shfl_xor_sync(0xffffffffu, q0, off);
                q1 += __shfl_xor_sync(0xffffffffu, q1, off);
            }
            if (lane < 4){
                atomicAdd(&sSum[nt*8 + lane*2],     s0);
                atomicAdd(&sSum[nt*8 + lane*2 + 1], s1);
                atomicAdd(&sSsq[nt*8 + lane*2],     q0);
                atomicAdd(&sSsq[nt*8 + lane*2 + 1], q1);
            }
        }
        __syncthreads();   // protect sX reuse + sums visibility
    }

    if (tid < 64){
        atomicAdd(&statsOut[tid],    sSum[tid]);
        atomicAdd(&statsOut[64+tid], sSsq[tid]);
    }
}

// ---------------- persistent final pooling + fused score ----------------
// grid = 148 blocks (all resident): chunk loop, grid barrier, then score.
__global__ void k_poolscore(const __half* __restrict__ Uh, const int* __restrict__ gid,
                            float* __restrict__ pooled,
                            const float* __restrict__ statsIn,
                            const float* __restrict__ gamma,
                            const float* __restrict__ beta,
                            const float* __restrict__ Wp, const float* __restrict__ bp,
                            float* __restrict__ out, int nblocks)
{
    __shared__ float sA[64], sB[64];
    int tid = threadIdx.x;
    bn_coeffs(statsIn, gamma, beta, sA, sB, tid);
    __syncthreads();
    int col  = tid & 63;
    int rl   = tid >> 6;
    float a = sA[col], b = sB[col];
    int nchunk = (Nn + 127)/128;
    for (int chunk = blockIdx.x; chunk < nchunk; chunk += nblocks){
        int base = chunk * 128 + rl*32;
        float acc = 0.f; int cur = -1;
        for (int j = 0; j < 32; j++){
            int r = base + j;
            if (r >= Nn) break;
            float x = __half2float(Uh[r*64 + col]);
            x = fmaxf(fmaf(x, a, b), 0.f);
            int gq = gid[r];
            if (gq != cur){
                if (cur >= 0) atomicAdd(&pooled[cur*64 + col], acc);
                cur = gq; acc = x;
            } else {
                acc += x;
            }
        }
        if (cur >= 0) atomicAdd(&pooled[cur*64 + col], acc);
    }

    // grid barrier, then score
    __syncthreads();
    if (tid == 0){
        __threadfence();
        atomicAdd(&g_poolCount, 1);
        while (atomicAdd(&g_poolCount, 0) < nblocks) { }
        __threadfence();
    }
    __syncthreads();

    int t = blockIdx.x*256 + tid;
    if (t < NG*16){
        int gg = t >> 4, o = t & 15;
        float acc = 0.f;
        #pragma unroll
        for (int i = 0; i < NPRED; i++){
            const float* __restrict__ P  = &g_pooled[(i*NG + gg)*64];
            const float* __restrict__ Wr = Wp + i*64*16 + o;
            float s = 0.f;
            #pragma unroll 16
            for (int k = 0; k < 64; k++) s = fmaf(P[k], Wr[k*16], s);
            acc += s + bp[i*16 + o];
        }
        out[t] = acc;
    }
}

// ---------------- launch ----------------
extern "C" void kernel_launch(void* const* d_in, const int* in_sizes, int n_in,
                              void* d_out, int out_size)
{
    const float* h    = (const float*)d_in[0];
    const int*   esrc = (const int*)  d_in[1];
    const int*   edst = (const int*)  d_in[2];
    const int*   gid  = (const int*)  d_in[3];
    const float* eps  = (const float*)d_in[4];
    const float* W1   = (const float*)d_in[5];
    const float* b1   = (const float*)d_in[6];
    const float* g1   = (const float*)d_in[7];
    const float* be1  = (const float*)d_in[8];
    const float* W2   = (const float*)d_in[9];
    const float* b2   = (const float*)d_in[10];
    const float* g2   = (const float*)d_in[11];
    const float* be2  = (const float*)d_in[12];
    const float* Wp   = (const float*)d_in[13];
    const float* bp   = (const float*)d_in[14];
    float* out = (float*)d_out;

    void *p_pooled, *p_pre16, *p_t16, *p_u16, *p_h16, *p_stats;
    cudaGetSymbolAddress(&p_pooled, g_pooled);
    cudaGetSymbolAddress(&p_pre16,  g_pre16);
    cudaGetSymbolAddress(&p_t16,    g_t16);
    cudaGetSymbolAddress(&p_u16,    g_u16);
    cudaGetSymbolAddress(&p_h16,    g_h16);
    cudaGetSymbolAddress(&p_stats,  g_stats);
    float* stats  = (float*)p_stats;
    float* pooled = (float*)p_pooled;

    // CSR by destination: hist(+rank+convert), fused scan+scatter
    k_hist<<<(Ee+255)/256, 256>>>(edst, h);
    int nb = (Nn + 1023)/1024;
    k_scanscatter<<<nb, 1024>>>(esrc, edst, nb);

    int aggB = Nn/16;

    for (int i = 0; i < NGIN; i++){
        float* s1 = stats + (2*i)*128;
        float* s2 = stats + (2*i+1)*128;

        if (i == 0)
            k_agg<0><<<aggB, 256>>>((const uint2*)p_h16, eps, 0, gid, pooled,
                                    nullptr, nullptr, nullptr);
        else
            k_agg<1><<<aggB, 256>>>((const uint2*)p_u16, eps, i, gid,
                                    pooled + (size_t)i*NG*Dd,
                                    stats + (2*(i-1)+1)*128,
                                    g2 + (i-1)*64, be2 + (i-1)*64);

        k_gemm<0><<<296, 256>>>((const uint4*)p_pre16, W1 + i*4096, b1 + i*64,
                                (unsigned*)p_t16, nullptr, s1, nullptr, nullptr);
        k_gemm<1><<<296, 256>>>((const uint4*)p_t16, W2 + i*4096, b2 + i*64,
                                (unsigned*)p_u16, s1, s2, g1 + i*64, be1 + i*64);
    }

    k_poolscore<<<148, 256>>>((const __half*)p_u16, gid,
                              pooled + (size_t)NGIN*NG*Dd,
                              stats + 7*128, g2 + 3*64, be2 + 3*64,
                              Wp, bp, out, 148);
}

// round 16
// speedup vs baseline: 1.0179x; 1.0179x over previous
#include <cuda_runtime.h>
#include <cuda_fp16.h>

#define Nn 100000
#define Ee 1200000
#define Dd 64
#define NGIN 4
#define NPRED 5
#define NG 512

// SW128 swizzle on byte offsets (bits [6:4] ^= bits [9:7])
#define SW(b) ((b) ^ (((b) >> 3) & 0x70))

__device__ __forceinline__ unsigned sptr(const void* p){
    return (unsigned)__cvta_generic_to_shared(p);
}
__device__ __forceinline__ void ldm_x4(unsigned addr, unsigned &r0, unsigned &r1,
                                       unsigned &r2, unsigned &r3){
    asm volatile("ldmatrix.sync.aligned.m8n8.x4.shared.b16 {%0,%1,%2,%3}, [%4];"
        : "=r"(r0),"=r"(r1),"=r"(r2),"=r"(r3) : "r"(addr));
}
__device__ __forceinline__ void ldm_x4t(unsigned addr, unsigned &r0, unsigned &r1,
                                        unsigned &r2, unsigned &r3){
    asm volatile("ldmatrix.sync.aligned.m8n8.x4.trans.shared.b16 {%0,%1,%2,%3}, [%4];"
        : "=r"(r0),"=r"(r1),"=r"(r2),"=r"(r3) : "r"(addr));
}
__device__ __forceinline__ void mma16816(float* d, const unsigned* a, unsigned b0, unsigned b1){
    asm volatile("mma.sync.aligned.m16n8k16.row.col.f32.f16.f16.f32 "
        "{%0,%1,%2,%3}, {%4,%5,%6,%7}, {%8,%9}, {%0,%1,%2,%3};"
        : "+f"(d[0]),"+f"(d[1]),"+f"(d[2]),"+f"(d[3])
        : "r"(a[0]),"r"(a[1]),"r"(a[2]),"r"(a[3]),"r"(b0),"r"(b1));
}

// ---------------- scratch ----------------
__device__ uint2 g_h16[Nn*16];      // input h as half2 (gather source, layer 0): 128 B/row
__device__ uint4 g_pre16[Nn*8];     // agg output, fp16 (GEMM1 input): 128 B/row
__device__ uint4 g_t16[Nn*8];       // GEMM1 output, fp16 (GEMM2 input, pre-BN)
__device__ uint4 g_u16[Nn*8];       // GEMM2 output, fp16 (gather source next layer / final pool)
__device__ int   g_deg[Nn];
__device__ int   g_rowptr[Nn+1];
__device__ int   g_rank[Ee];        // within-destination rank of each edge
__device__ int   g_col[Ee];         // pre-scaled: src*16 (uint2 row offset)
__device__ int   g_bsum[128];
__device__ int   g_scanCount;       // scan barrier counter (reset in k_hist)
__device__ int   g_poolCount;       // pool/score barrier counter (reset in k_hist)
__device__ float g_stats[8*128];    // 8 slots: [0:64) sum, [64:128) sumsq
__device__ float g_pooled[NPRED*NG*Dd];

// ---------------- CSR hist + rank + h->fp16 conversion + zeroing ----------------
__global__ void k_hist(const int* __restrict__ dst, const float* __restrict__ h){
    int i = blockIdx.x*blockDim.x + threadIdx.x;
    int nthr = gridDim.x*blockDim.x;
    if (i < Ee){
        int r = atomicAdd(&g_deg[dst[i]], 1);
        g_rank[i] = r;
    }
    const float4* h4 = (const float4*)h;
    for (int j = i; j < Nn*16; j += nthr){
        float4 x = h4[j];
        __half2 p0 = __float22half2_rn(make_float2(x.x, x.y));
        __half2 p1 = __float22half2_rn(make_float2(x.z, x.w));
        uint2 o;
        o.x = *(unsigned*)&p0;
        o.y = *(unsigned*)&p1;
        g_h16[j] = o;
    }
    if (i < NPRED*NG*Dd) g_pooled[i] = 0.f;
    if (i < 8*128) g_stats[i] = 0.f;
    if (i == 0){ g_scanCount = 0; g_poolCount = 0; }
}

// single-kernel scan: phase 1 local scan + bsum, resident-grid barrier, phase 2 prefix.
__global__ void k_scan(int nb){
    __shared__ int s[1024];
    __shared__ int sb[128];
    int b = blockIdx.x;
    int i = b*1024 + threadIdx.x;
    int v = 0;
    if (i < Nn){ v = g_deg[i]; g_deg[i] = 0; }   // self-clean for next replay
    s[threadIdx.x] = v;
    __syncthreads();
    #pragma unroll
    for (int off = 1; off < 1024; off <<= 1){
        int x = (threadIdx.x >= off) ? s[threadIdx.x - off] : 0;
        __syncthreads();
        s[threadIdx.x] += x;
        __syncthreads();
    }
    if (threadIdx.x == 1023){
        g_bsum[b] = s[1023];
        __threadfence();
    }
    __syncthreads();
    if (threadIdx.x == 0){
        atomicAdd(&g_scanCount, 1);
        while (atomicAdd(&g_scanCount, 0) < nb) { }
        __threadfence();
    }
    __syncthreads();

    if (threadIdx.x < 128) sb[threadIdx.x] = (threadIdx.x < nb) ? g_bsum[threadIdx.x] : 0;
    __syncthreads();
    #pragma unroll
    for (int off = 1; off < 128; off <<= 1){
        int x = 0;
        if (threadIdx.x < 128 && threadIdx.x >= off) x = sb[threadIdx.x - off];
        __syncthreads();
        if (threadIdx.x < 128) sb[threadIdx.x] += x;
        __syncthreads();
    }
    int excl = (b > 0) ? sb[b-1] : 0;
    if (i < Nn) g_rowptr[i+1] = s[threadIdx.x] + excl;
    if (i == 0) g_rowptr[0] = 0;
}

// atomic-free scatter: position = rowptr[dst] + rank
__global__ void k_scatter(const int* __restrict__ src, const int* __restrict__ dst){
    int i = blockIdx.x*blockDim.x + threadIdx.x;
    if (i < Ee){
        int p = g_rowptr[dst[i]] + g_rank[i];
        g_col[p] = src[i] * 16;      // pre-scaled uint2 row offset
    }
}

// ---------------- per-block BN coefficient computation ----------------
__device__ __forceinline__ void bn_coeffs(const float* __restrict__ stats,
                                          const float* __restrict__ gamma,
                                          const float* __restrict__ beta,
                                          float* sA, float* sB, int tid)
{
    if (tid < 64){
        float m = stats[tid]    * (1.f/Nn);
        float v = stats[64+tid] * (1.f/Nn) - m*m;
        float a = gamma[tid] * rsqrtf(v + 1e-5f);
        sA[tid] = a;
        sB[tid] = beta[tid] - m*a;
    }
}

// ---------------- aggregation: TWO nodes per warp (16 lanes x 4 halfs each),
// fp16 gather, pipelined col prefetch, half2 BN+relu, fused pooling (R13 proven) ----------------
template<int MODE>
__global__ void __launch_bounds__(256) k_agg(const uint2* __restrict__ hh,
                                             const float* __restrict__ eps, int layer,
                                             const int* __restrict__ gid,
                                             float* __restrict__ pooled,
                                             const float* __restrict__ statsIn,
                                             const float* __restrict__ gamma,
                                             const float* __restrict__ beta)
{
    __shared__ float sA[64], sB[64];
    __shared__ float sPool[16][64];
    __shared__ int   sGid[16];
    int tid  = threadIdx.x;
    int wp   = tid >> 5;
    int lane = tid & 31;
    int half = lane >> 4;
    int hl   = lane & 15;
    int nl   = wp*2 + half;              // 0..15 node within block
    int w    = blockIdx.x*16 + nl;       // Nn % 16 == 0 -> always valid

    if (MODE){
        bn_coeffs(statsIn, gamma, beta, sA, sB, tid);
        __syncthreads();
    }

    int c0 = hl*4;
    __half2 A0 = __float2half2_rn(1.f), A1 = A0;
    __half2 B0 = __float2half2_rn(0.f), B1 = B0;
    const __half2 Z2 = __float2half2_rn(0.f);
    if (MODE){
        A0 = __floats2half2_rn(sA[c0],   sA[c0+1]);
        A1 = __floats2half2_rn(sA[c0+2], sA[c0+3]);
        B0 = __floats2half2_rn(sB[c0],   sB[c0+1]);
        B1 = __floats2half2_rn(sB[c0+2], sB[c0+3]);
    }
    float epv = 1.f + eps[layer];

    uint2 sv = hh[w*16 + hl];
    __half2 s0 = *(__half2*)&sv.x, s1 = *(__half2*)&sv.y;
    if (MODE){
        s0 = __hmax2(__hfma2(s0, A0, B0), Z2);
        s1 = __hmax2(__hfma2(s1, A1, B1), Z2);
    }
    float2 f0 = __half22float2(s0), f1 = __half22float2(s1);
    *(float2*)&sPool[nl][c0]     = f0;
    *(float2*)&sPool[nl][c0 + 2] = f1;
    if (hl == 0) sGid[nl] = gid[w];

    float ax0 = f0.x*epv, ax1 = f0.y*epv, ax2 = f1.x*epv, ax3 = f1.y*epv;
    int e = g_rowptr[w], end = g_rowptr[w+1];

    int o0=0, o1=0, o2=0, o3=0;
    bool have = (e + 4 <= end);
    if (have){ o0 = g_col[e]; o1 = g_col[e+1]; o2 = g_col[e+2]; o3 = g_col[e+3]; }
    while (have){
        int p0=0, p1=0, p2=0, p3=0;
        bool nxt = (e + 8 <= end);
        if (nxt){ p0 = g_col[e+4]; p1 = g_col[e+5]; p2 = g_col[e+6]; p3 = g_col[e+7]; }
        uint2 v0 = hh[o0+hl], v1 = hh[o1+hl], v2 = hh[o2+hl], v3 = hh[o3+hl];
        __half2 a0 = *(__half2*)&v0.x, b0 = *(__half2*)&v0.y;
        __half2 a1 = *(__half2*)&v1.x, b1 = *(__half2*)&v1.y;
        __half2 a2 = *(__half2*)&v2.x, b2 = *(__half2*)&v2.y;
        __half2 a3 = *(__half2*)&v3.x, b3 = *(__half2*)&v3.y;
        if (MODE){
            a0 = __hmax2(__hfma2(a0,A0,B0),Z2); b0 = __hmax2(__hfma2(b0,A1,B1),Z2);
            a1 = __hmax2(__hfma2(a1,A0,B0),Z2); b1 = __hmax2(__hfma2(b1,A1,B1),Z2);
            a2 = __hmax2(__hfma2(a2,A0,B0),Z2); b2 = __hmax2(__hfma2(b2,A1,B1),Z2);
            a3 = __hmax2(__hfma2(a3,A0,B0),Z2); b3 = __hmax2(__hfma2(b3,A1,B1),Z2);
        }
        float2 g0 = __half22float2(a0), h0 = __half22float2(b0);
        float2 g1 = __half22float2(a1), h1 = __half22float2(b1);
        float2 g2 = __half22float2(a2), h2 = __half22float2(b2);
        float2 g3 = __half22float2(a3), h3 = __half22float2(b3);
        ax0 += (g0.x + g1.x) + (g2.x + g3.x);
        ax1 += (g0.y + g1.y) + (g2.y + g3.y);
        ax2 += (h0.x + h1.x) + (h2.x + h3.x);
        ax3 += (h0.y + h1.y) + (h2.y + h3.y);
        o0 = p0; o1 = p1; o2 = p2; o3 = p3;
        e += 4;
        have = nxt;
    }
    for (; e < end; e++){
        uint2 v = hh[g_col[e] + hl];
        __half2 a = *(__half2*)&v.x, b = *(__half2*)&v.y;
        if (MODE){
            a = __hmax2(__hfma2(a,A0,B0),Z2);
            b = __hmax2(__hfma2(b,A1,B1),Z2);
        }
        float2 g = __half22float2(a), hq = __half22float2(b);
        ax0 += g.x; ax1 += g.y; ax2 += hq.x; ax3 += hq.y;
    }

    __half2 r0 = __floats2half2_rn(ax0, ax1);
    __half2 r1 = __floats2half2_rn(ax2, ax3);
    uint2 ov; ov.x = *(unsigned*)&r0; ov.y = *(unsigned*)&r1;
    ((uint2*)g_pre16)[w*16 + hl] = ov;

    __syncthreads();
    if (tid < 64){
        float acc = sPool[0][tid];
        int cur = sGid[0];
        #pragma unroll
        for (int r = 1; r < 16; r++){
            int g = sGid[r];
            if (g != cur){
                atomicAdd(&pooled[cur*64 + tid], acc);
                cur = g; acc = sPool[r][tid];
            } else {
                acc += sPool[r][tid];
            }
        }
        atomicAdd(&pooled[cur*64 + tid], acc);
    }
}

// ---------------- HMMA GEMM (R13 proven): (256 rows/block x 64) @ (64 x 64) + bias,
// fp16 in/out, fp32 acc, fused BN-stats; optional fused BN+relu on INPUT ----------------
template<int APPLY>
__global__ void __launch_bounds__(256, 2) k_gemm(const uint4* __restrict__ X16,
                                                 const float* __restrict__ W,
                                                 const float* __restrict__ bias,
                                                 unsigned* __restrict__ Y,   // half2 units
                                                 const float* __restrict__ statsIn,
                                                 float* __restrict__ statsOut,
                                                 const float* __restrict__ gamma,
                                                 const float* __restrict__ beta)
{
    __shared__ uint4 sX4[256*8];
    __shared__ uint4 sW4[64*8];
    __shared__ float sA[64], sB[64], sBias[64];
    __shared__ float sSum[64], sSsq[64];
    char* sX  = (char*)sX4;
    char* sWt = (char*)sW4;
    int tid = threadIdx.x;
    int rowBase = blockIdx.x * 256;
    if (tid < 64){ sSum[tid] = 0.f; sSsq[tid] = 0.f; sBias[tid] = bias[tid]; }
    if (APPLY) bn_coeffs(statsIn, gamma, beta, sA, sB, tid);

    {
        const float2* W2 = (const float2*)W;
        #pragma unroll
        for (int it = 0; it < 8; it++){
            int idx = tid + it*256;
            int k  = idx >> 5;
            int n2 = idx & 31;
            __half2 hw = __float22half2_rn(W2[idx]);
            *(unsigned*)(sWt + SW(k*128 + n2*4)) = *(unsigned*)&hw;
        }
    }
    __syncthreads();

    #pragma unroll
    for (int it = 0; it < 8; it++){
        int idx = tid + it*256;
        int r = idx >> 3;
        int c = idx & 7;
        int gr = rowBase + r;
        uint4 v = make_uint4(0,0,0,0);
        if (gr < Nn){
            v = X16[gr*8 + c];
            if (APPLY){
                __half2* ph = (__half2*)&v;
                #pragma unroll
                for (int q = 0; q < 4; q++){
                    float2 f = __half22float2(ph[q]);
                    int col = c*8 + q*2;
                    f.x = fmaxf(fmaf(f.x, sA[col],   sB[col]),   0.f);
                    f.y = fmaxf(fmaf(f.y, sA[col+1], sB[col+1]), 0.f);
                    ph[q] = __float22half2_rn(f);
                }
            }
        }
        *(uint4*)(sX + SW(r*128 + c*16)) = v;
    }
    __syncthreads();

    int wid  = tid >> 5;
    int lane = tid & 31;
    int warpRow = wid * 32;
    unsigned sXb = sptr(sX);
    unsigned sWb = sptr(sWt);

    float acc[2][8][4];
    #pragma unroll
    for (int mt = 0; mt < 2; mt++)
        #pragma unroll
        for (int nt = 0; nt < 8; nt++)
            #pragma unroll
            for (int q = 0; q < 4; q++) acc[mt][nt][q] = 0.f;

    int sel = lane >> 3;
    int lr  = lane & 7;
    #pragma unroll
    for (int ks = 0; ks < 4; ks++){
        unsigned a[2][4];
        #pragma unroll
        for (int mt = 0; mt < 2; mt++){
            int rowl = warpRow + mt*16 + lr + ((sel & 1) << 3);
            int kb   = ks*32 + ((sel >> 1) << 4);
            ldm_x4(sXb + SW(rowl*128 + kb), a[mt][0], a[mt][1], a[mt][2], a[mt][3]);
        }
        #pragma unroll
        for (int j = 0; j < 4; j++){
            int kr = ks*16 + lr + ((sel & 1) << 3);
            int nb = j*32 + ((sel >> 1) << 4);
            unsigned b0, b1, b2, b3;
            ldm_x4t(sWb + SW(kr*128 + nb), b0, b1, b2, b3);
            mma16816(acc[0][2*j],   a[0], b0, b1);
            mma16816(acc[1][2*j],   a[1], b0, b1);
            mma16816(acc[0][2*j+1], a[0], b2, b3);
            mma16816(acc[1][2*j+1], a[1], b2, b3);
        }
    }

    int g  = lane >> 2;
    int i4 = lane & 3;
    int i2 = i4 * 2;
    #pragma unroll
    for (int nt = 0; nt < 8; nt++){
        float b0f = sBias[nt*8 + i2];
        float b1f = sBias[nt*8 + i2 + 1];
        float s0 = 0.f, s1 = 0.f, q0 = 0.f, q1 = 0.f;
        #pragma unroll
        for (int mt = 0; mt < 2; mt++){
            int row0 = rowBase + warpRow + mt*16 + g;
            float d0 = acc[mt][nt][0] + b0f;
            float d1 = acc[mt][nt][1] + b1f;
            float d2 = acc[mt][nt][2] + b0f;
            float d3 = acc[mt][nt][3] + b1f;
            if (row0 < Nn){
                __half2 hv = __float22half2_rn(make_float2(d0, d1));
                Y[row0*32 + nt*4 + i4] = *(unsigned*)&hv;
                s0 += d0; s1 += d1; q0 += d0*d0; q1 += d1*d1;
            }
            if (row0 + 8 < Nn){
                __half2 hv = __float22half2_rn(make_float2(d2, d3));
                Y[(row0+8)*32 + nt*4 + i4] = *(unsigned*)&hv;
                s0 += d2; s1 += d3; q0 += d2*d2; q1 += d3*d3;
            }
        }
        #pragma unroll
        for (int off = 4; off < 32; off <<= 1){
            s0 += __shfl_xor_sync(0xffffffffu, s0, off);
            s1 += __shfl_xor_sync(0xffffffffu, s1, off);
            q0 += __shfl_xor_sync(0xffffffffu, q0, off);
            q1 += __shfl_xor_sync(0xffffffffu, q1, off);
        }
        if (lane < 4){
            atomicAdd(&sSum[nt*8 + lane*2],     s0);
            atomicAdd(&sSum[nt*8 + lane*2 + 1], s1);
            atomicAdd(&sSsq[nt*8 + lane*2],     q0);
            atomicAdd(&sSsq[nt*8 + lane*2 + 1], q1);
        }
    }
    __syncthreads();
    if (tid < 64){
        atomicAdd(&statsOut[tid],    sSum[tid]);
        atomicAdd(&statsOut[64+tid], sSsq[tid]);
    }
}

// ---------------- persistent final pooling + fused score (148 resident blocks) ----------------
__global__ void k_poolscore(const __half* __restrict__ Uh, const int* __restrict__ gid,
                            float* __restrict__ pooled,
                            const float* __restrict__ statsIn,
                            const float* __restrict__ gamma,
                            const float* __restrict__ beta,
                            const float* __restrict__ Wp, const float* __restrict__ bp,
                            float* __restrict__ out, int nblocks)
{
    __shared__ float sA[64], sB[64];
    int tid = threadIdx.x;
    bn_coeffs(statsIn, gamma, beta, sA, sB, tid);
    __syncthreads();
    int col  = tid & 63;
    int rl   = tid >> 6;
    float a = sA[col], b = sB[col];
    int nchunk = (Nn + 127)/128;
    for (int chunk = blockIdx.x; chunk < nchunk; chunk += nblocks){
        int base = chunk * 128 + rl*32;
        float acc = 0.f; int cur = -1;
        for (int j = 0; j < 32; j++){
            int r = base + j;
            if (r >= Nn) break;
            float x = __half2float(Uh[r*64 + col]);
            x = fmaxf(fmaf(x, a, b), 0.f);
            int gq = gid[r];
            if (gq != cur){
                if (cur >= 0) atomicAdd(&pooled[cur*64 + col], acc);
                cur = gq; acc = x;
            } else {
                acc += x;
            }
        }
        if (cur >= 0) atomicAdd(&pooled[cur*64 + col], acc);
    }

    // grid barrier, then score on the first NG*16 threads
    __syncthreads();
    if (tid == 0){
        __threadfence();
        atomicAdd(&g_poolCount, 1);
        while (atomicAdd(&g_poolCount, 0) < nblocks) { }
        __threadfence();
    }
    __syncthreads();

    int t = blockIdx.x*256 + tid;
    if (t < NG*16){
        int gg = t >> 4, o = t & 15;
        float acc = 0.f;
        #pragma unroll
        for (int i = 0; i < NPRED; i++){
            const float* __restrict__ P  = &g_pooled[(i*NG + gg)*64];
            const float* __restrict__ Wr = Wp + i*64*16 + o;
            float s = 0.f;
            #pragma unroll 16
            for (int k = 0; k < 64; k++) s = fmaf(P[k], Wr[k*16], s);
            acc += s + bp[i*16 + o];
        }
        out[t] = acc;
    }
}

// ---------------- launch ----------------
extern "C" void kernel_launch(void* const* d_in, const int* in_sizes, int n_in,
                              void* d_out, int out_size)
{
    const float* h    = (const float*)d_in[0];
    const int*   esrc = (const int*)  d_in[1];
    const int*   edst = (const int*)  d_in[2];
    const int*   gid  = (const int*)  d_in[3];
    const float* eps  = (const float*)d_in[4];
    const float* W1   = (const float*)d_in[5];
    const float* b1   = (const float*)d_in[6];
    const float* g1   = (const float*)d_in[7];
    const float* be1  = (const float*)d_in[8];
    const float* W2   = (const float*)d_in[9];
    const float* b2   = (const float*)d_in[10];
    const float* g2   = (const float*)d_in[11];
    const float* be2  = (const float*)d_in[12];
    const float* Wp   = (const float*)d_in[13];
    const float* bp   = (const float*)d_in[14];
    float* out = (float*)d_out;

    void *p_pooled, *p_pre16, *p_t16, *p_u16, *p_h16, *p_stats;
    cudaGetSymbolAddress(&p_pooled, g_pooled);
    cudaGetSymbolAddress(&p_pre16,  g_pre16);
    cudaGetSymbolAddress(&p_t16,    g_t16);
    cudaGetSymbolAddress(&p_u16,    g_u16);
    cudaGetSymbolAddress(&p_h16,    g_h16);
    cudaGetSymbolAddress(&p_stats,  g_stats);
    float* stats  = (float*)p_stats;
    float* pooled = (float*)p_pooled;

    // CSR by destination: hist(+rank+convert), fused scan, atomic-free scatter
    k_hist<<<(Ee+255)/256, 256>>>(edst, h);
    int nb = (Nn + 1023)/1024;
    k_scan<<<nb, 1024>>>(nb);
    k_scatter<<<(Ee+255)/256, 256>>>(esrc, edst);

    int gemmB_ = (Nn + 255)/256;
    int aggB   = Nn/16;

    for (int i = 0; i < NGIN; i++){
        float* s1 = stats + (2*i)*128;
        float* s2 = stats + (2*i+1)*128;

        if (i == 0)
            k_agg<0><<<aggB, 256>>>((const uint2*)p_h16, eps, 0, gid, pooled,
                                    nullptr, nullptr, nullptr);
        else
            k_agg<1><<<aggB, 256>>>((const uint2*)p_u16, eps, i, gid,
                                    pooled + (size_t)i*NG*Dd,
                                    stats + (2*(i-1)+1)*128,
                                    g2 + (i-1)*64, be2 + (i-1)*64);

        k_gemm<0><<<gemmB_, 256>>>((const uint4*)p_pre16, W1 + i*4096, b1 + i*64,
                                   (unsigned*)p_t16, nullptr, s1, nullptr, nullptr);
        k_gemm<1><<<gemmB_, 256>>>((const uint4*)p_t16, W2 + i*4096, b2 + i*64,
                                   (unsigned*)p_u16, s1, s2, g1 + i*64, be1 + i*64);
    }

    k_poolscore<<<148, 256>>>((const __half*)p_u16, gid,
                              pooled + (size_t)NGIN*NG*Dd,
                              stats + 7*128, g2 + 3*64, be2 + 3*64,
                              Wp, bp, out, 148);
}

// round 17
// speedup vs baseline: 1.1939x; 1.1729x over previous
#include <cuda_runtime.h>
#include <cuda_fp16.h>

#define Nn 100000
#define Ee 1200000
#define Dd 64
#define NGIN 4
#define NPRED 5
#define NG 512

// SW128 swizzle on byte offsets (bits [6:4] ^= bits [9:7])
#define SW(b) ((b) ^ (((b) >> 3) & 0x70))

__device__ __forceinline__ unsigned sptr(const void* p){
    return (unsigned)__cvta_generic_to_shared(p);
}
__device__ __forceinline__ void ldm_x4(unsigned addr, unsigned &r0, unsigned &r1,
                                       unsigned &r2, unsigned &r3){
    asm volatile("ldmatrix.sync.aligned.m8n8.x4.shared.b16 {%0,%1,%2,%3}, [%4];"
        : "=r"(r0),"=r"(r1),"=r"(r2),"=r"(r3) : "r"(addr));
}
__device__ __forceinline__ void ldm_x4t(unsigned addr, unsigned &r0, unsigned &r1,
                                        unsigned &r2, unsigned &r3){
    asm volatile("ldmatrix.sync.aligned.m8n8.x4.trans.shared.b16 {%0,%1,%2,%3}, [%4];"
        : "=r"(r0),"=r"(r1),"=r"(r2),"=r"(r3) : "r"(addr));
}
__device__ __forceinline__ void mma16816(float* d, const unsigned* a, unsigned b0, unsigned b1){
    asm volatile("mma.sync.aligned.m16n8k16.row.col.f32.f16.f16.f32 "
        "{%0,%1,%2,%3}, {%4,%5,%6,%7}, {%8,%9}, {%0,%1,%2,%3};"
        : "+f"(d[0]),"+f"(d[1]),"+f"(d[2]),"+f"(d[3])
        : "r"(a[0]),"r"(a[1]),"r"(a[2]),"r"(a[3]),"r"(b0),"r"(b1));
}

// ---------------- scratch ----------------
__device__ uint2 g_h16[Nn*16];      // input h as half2 (gather source, layer 0): 128 B/row
__device__ uint4 g_pre16[Nn*8];     // agg output, fp16 (GEMM1 input): 128 B/row
__device__ uint4 g_t16[Nn*8];       // GEMM1 output, fp16 (GEMM2 input, pre-BN)
__device__ uint4 g_u16[Nn*8];       // GEMM2 output, fp16 (gather source next layer / final pool)
__device__ int   g_deg[Nn];
__device__ int   g_rowptr[Nn+1];
__device__ int   g_rank[Ee];        // within-destination rank of each edge
__device__ int   g_col[Ee];         // pre-scaled: src*16 (uint2 row offset)
__device__ int   g_bsum[128];
__device__ int   g_scanCount;       // scan barrier counter (reset in k_hist)
__device__ float g_stats[8*128];    // 8 slots: [0:64) sum, [64:128) sumsq
__device__ float g_pooled[NPRED*NG*Dd];

// ---------------- CSR hist + rank + h->fp16 conversion + zeroing ----------------
__global__ void k_hist(const int* __restrict__ dst, const float* __restrict__ h){
    int i = blockIdx.x*blockDim.x + threadIdx.x;
    int nthr = gridDim.x*blockDim.x;
    if (i < Ee){
        int r = atomicAdd(&g_deg[dst[i]], 1);
        g_rank[i] = r;
    }
    const float4* h4 = (const float4*)h;
    for (int j = i; j < Nn*16; j += nthr){
        float4 x = h4[j];
        __half2 p0 = __float22half2_rn(make_float2(x.x, x.y));
        __half2 p1 = __float22half2_rn(make_float2(x.z, x.w));
        uint2 o;
        o.x = *(unsigned*)&p0;
        o.y = *(unsigned*)&p1;
        g_h16[j] = o;
    }
    if (i < NPRED*NG*Dd) g_pooled[i] = 0.f;
    if (i < 8*128) g_stats[i] = 0.f;
    if (i == 0) g_scanCount = 0;
}

// single-kernel scan: phase 1 local scan + bsum, resident-grid barrier, phase 2 prefix.
__global__ void k_scan(int nb){
    __shared__ int s[1024];
    __shared__ int sb[128];
    int b = blockIdx.x;
    int i = b*1024 + threadIdx.x;
    int v = 0;
    if (i < Nn){ v = g_deg[i]; g_deg[i] = 0; }   // self-clean for next replay
    s[threadIdx.x] = v;
    __syncthreads();
    #pragma unroll
    for (int off = 1; off < 1024; off <<= 1){
        int x = (threadIdx.x >= off) ? s[threadIdx.x - off] : 0;
        __syncthreads();
        s[threadIdx.x] += x;
        __syncthreads();
    }
    if (threadIdx.x == 1023){
        g_bsum[b] = s[1023];
        __threadfence();
    }
    __syncthreads();
    if (threadIdx.x == 0){
        atomicAdd(&g_scanCount, 1);
        while (atomicAdd(&g_scanCount, 0) < nb) { }
        __threadfence();
    }
    __syncthreads();

    if (threadIdx.x < 128) sb[threadIdx.x] = (threadIdx.x < nb) ? g_bsum[threadIdx.x] : 0;
    __syncthreads();
    #pragma unroll
    for (int off = 1; off < 128; off <<= 1){
        int x = 0;
        if (threadIdx.x < 128 && threadIdx.x >= off) x = sb[threadIdx.x - off];
        __syncthreads();
        if (threadIdx.x < 128) sb[threadIdx.x] += x;
        __syncthreads();
    }
    int excl = (b > 0) ? sb[b-1] : 0;
    if (i < Nn) g_rowptr[i+1] = s[threadIdx.x] + excl;
    if (i == 0) g_rowptr[0] = 0;
}

// atomic-free scatter: position = rowptr[dst] + rank
__global__ void k_scatter(const int* __restrict__ src, const int* __restrict__ dst){
    int i = blockIdx.x*blockDim.x + threadIdx.x;
    if (i < Ee){
        int p = g_rowptr[dst[i]] + g_rank[i];
        g_col[p] = src[i] * 16;      // pre-scaled uint2 row offset
    }
}

// ---------------- per-block BN coefficient computation ----------------
__device__ __forceinline__ void bn_coeffs(const float* __restrict__ stats,
                                          const float* __restrict__ gamma,
                                          const float* __restrict__ beta,
                                          float* sA, float* sB, int tid)
{
    if (tid < 64){
        float m = stats[tid]    * (1.f/Nn);
        float v = stats[64+tid] * (1.f/Nn) - m*m;
        float a = gamma[tid] * rsqrtf(v + 1e-5f);
        sA[tid] = a;
        sB[tid] = beta[tid] - m*a;
    }
}

// ---------------- aggregation: TWO nodes per warp, fp16 gather, pipelined col prefetch,
// half2 BN+relu, PAIRWISE HADD2 reduction into scalar f32 accumulators, fused pooling ----------------
template<int MODE>
__global__ void __launch_bounds__(256) k_agg(const uint2* __restrict__ hh,
                                             const float* __restrict__ eps, int layer,
                                             const int* __restrict__ gid,
                                             float* __restrict__ pooled,
                                             const float* __restrict__ statsIn,
                                             const float* __restrict__ gamma,
                                             const float* __restrict__ beta)
{
    __shared__ float sA[64], sB[64];
    __shared__ float sPool[16][64];
    __shared__ int   sGid[16];
    int tid  = threadIdx.x;
    int wp   = tid >> 5;
    int lane = tid & 31;
    int half = lane >> 4;
    int hl   = lane & 15;
    int nl   = wp*2 + half;              // 0..15 node within block
    int w    = blockIdx.x*16 + nl;       // Nn % 16 == 0 -> always valid

    if (MODE){
        bn_coeffs(statsIn, gamma, beta, sA, sB, tid);
        __syncthreads();
    }

    int c0 = hl*4;
    __half2 A0 = __float2half2_rn(1.f), A1 = A0;
    __half2 B0 = __float2half2_rn(0.f), B1 = B0;
    const __half2 Z2 = __float2half2_rn(0.f);
    if (MODE){
        A0 = __floats2half2_rn(sA[c0],   sA[c0+1]);
        A1 = __floats2half2_rn(sA[c0+2], sA[c0+3]);
        B0 = __floats2half2_rn(sB[c0],   sB[c0+1]);
        B1 = __floats2half2_rn(sB[c0+2], sB[c0+3]);
    }
    float epv = 1.f + eps[layer];

    uint2 sv = hh[w*16 + hl];
    __half2 s0 = *(__half2*)&sv.x, s1 = *(__half2*)&sv.y;
    if (MODE){
        s0 = __hmax2(__hfma2(s0, A0, B0), Z2);
        s1 = __hmax2(__hfma2(s1, A1, B1), Z2);
    }
    float2 f0 = __half22float2(s0), f1 = __half22float2(s1);
    *(float2*)&sPool[nl][c0]     = f0;
    *(float2*)&sPool[nl][c0 + 2] = f1;
    if (hl == 0) sGid[nl] = gid[w];

    float ax0 = f0.x*epv, ax1 = f0.y*epv, ax2 = f1.x*epv, ax3 = f1.y*epv;
    int e = g_rowptr[w], end = g_rowptr[w+1];

    int o0=0, o1=0, o2=0, o3=0;
    bool have = (e + 4 <= end);
    if (have){ o0 = g_col[e]; o1 = g_col[e+1]; o2 = g_col[e+2]; o3 = g_col[e+3]; }
    while (have){
        int p0=0, p1=0, p2=0, p3=0;
        bool nxt = (e + 8 <= end);
        if (nxt){ p0 = g_col[e+4]; p1 = g_col[e+5]; p2 = g_col[e+6]; p3 = g_col[e+7]; }
        uint2 v0 = hh[o0+hl], v1 = hh[o1+hl], v2 = hh[o2+hl], v3 = hh[o3+hl];
        __half2 a0 = *(__half2*)&v0.x, b0 = *(__half2*)&v0.y;
        __half2 a1 = *(__half2*)&v1.x, b1 = *(__half2*)&v1.y;
        __half2 a2 = *(__half2*)&v2.x, b2 = *(__half2*)&v2.y;
        __half2 a3 = *(__half2*)&v3.x, b3 = *(__half2*)&v3.y;
        if (MODE){
            a0 = __hmax2(__hfma2(a0,A0,B0),Z2); b0 = __hmax2(__hfma2(b0,A1,B1),Z2);
            a1 = __hmax2(__hfma2(a1,A0,B0),Z2); b1 = __hmax2(__hfma2(b1,A1,B1),Z2);
            a2 = __hmax2(__hfma2(a2,A0,B0),Z2); b2 = __hmax2(__hfma2(b2,A1,B1),Z2);
            a3 = __hmax2(__hfma2(a3,A0,B0),Z2); b3 = __hmax2(__hfma2(b3,A1,B1),Z2);
        }
        // pairwise fp16 add (ONE extra fp16 rounding per element), then cvt + scalar f32 adds
        __half2 tA0 = __hadd2(a0, a1);
        __half2 tA1 = __hadd2(a2, a3);
        __half2 tB0 = __hadd2(b0, b1);
        __half2 tB1 = __hadd2(b2, b3);
        float2 fA0 = __half22float2(tA0);
        float2 fA1 = __half22float2(tA1);
        float2 fB0 = __half22float2(tB0);
        float2 fB1 = __half22float2(tB1);
        ax0 += fA0.x + fA1.x;
        ax1 += fA0.y + fA1.y;
        ax2 += fB0.x + fB1.x;
        ax3 += fB0.y + fB1.y;
        o0 = p0; o1 = p1; o2 = p2; o3 = p3;
        e += 4;
        have = nxt;
    }
    for (; e < end; e++){
        uint2 v = hh[g_col[e] + hl];
        __half2 a = *(__half2*)&v.x, b = *(__half2*)&v.y;
        if (MODE){
            a = __hmax2(__hfma2(a,A0,B0),Z2);
            b = __hmax2(__hfma2(b,A1,B1),Z2);
        }
        float2 g = __half22float2(a), hq = __half22float2(b);
        ax0 += g.x; ax1 += g.y; ax2 += hq.x; ax3 += hq.y;
    }

    __half2 r0 = __floats2half2_rn(ax0, ax1);
    __half2 r1 = __floats2half2_rn(ax2, ax3);
    uint2 ov; ov.x = *(unsigned*)&r0; ov.y = *(unsigned*)&r1;
    ((uint2*)g_pre16)[w*16 + hl] = ov;

    __syncthreads();
    if (tid < 64){
        float acc = sPool[0][tid];
        int cur = sGid[0];
        #pragma unroll
        for (int r = 1; r < 16; r++){
            int g = sGid[r];
            if (g != cur){
                atomicAdd(&pooled[cur*64 + tid], acc);
                cur = g; acc = sPool[r][tid];
            } else {
                acc += sPool[r][tid];
            }
        }
        atomicAdd(&pooled[cur*64 + tid], acc);
    }
}

// ---------------- HMMA GEMM (R13 proven): (256 rows/block x 64) @ (64 x 64) + bias,
// fp16 in/out, fp32 acc, fused BN-stats; optional fused BN+relu on INPUT ----------------
template<int APPLY>
__global__ void __launch_bounds__(256, 2) k_gemm(const uint4* __restrict__ X16,
                                                 const float* __restrict__ W,
                                                 const float* __restrict__ bias,
                                                 unsigned* __restrict__ Y,   // half2 units
                                                 const float* __restrict__ statsIn,
                                                 float* __restrict__ statsOut,
                                                 const float* __restrict__ gamma,
                                                 const float* __restrict__ beta)
{
    __shared__ uint4 sX4[256*8];
    __shared__ uint4 sW4[64*8];
    __shared__ float sA[64], sB[64], sBias[64];
    __shared__ float sSum[64], sSsq[64];
    char* sX  = (char*)sX4;
    char* sWt = (char*)sW4;
    int tid = threadIdx.x;
    int rowBase = blockIdx.x * 256;
    if (tid < 64){ sSum[tid] = 0.f; sSsq[tid] = 0.f; sBias[tid] = bias[tid]; }
    if (APPLY) bn_coeffs(statsIn, gamma, beta, sA, sB, tid);

    {
        const float2* W2 = (const float2*)W;
        #pragma unroll
        for (int it = 0; it < 8; it++){
            int idx = tid + it*256;
            int k  = idx >> 5;
            int n2 = idx & 31;
            __half2 hw = __float22half2_rn(W2[idx]);
            *(unsigned*)(sWt + SW(k*128 + n2*4)) = *(unsigned*)&hw;
        }
    }
    __syncthreads();

    #pragma unroll
    for (int it = 0; it < 8; it++){
        int idx = tid + it*256;
        int r = idx >> 3;
        int c = idx & 7;
        int gr = rowBase + r;
        uint4 v = make_uint4(0,0,0,0);
        if (gr < Nn){
            v = X16[gr*8 + c];
            if (APPLY){
                __half2* ph = (__half2*)&v;
                #pragma unroll
                for (int q = 0; q < 4; q++){
                    float2 f = __half22float2(ph[q]);
                    int col = c*8 + q*2;
                    f.x = fmaxf(fmaf(f.x, sA[col],   sB[col]),   0.f);
                    f.y = fmaxf(fmaf(f.y, sA[col+1], sB[col+1]), 0.f);
                    ph[q] = __float22half2_rn(f);
                }
            }
        }
        *(uint4*)(sX + SW(r*128 + c*16)) = v;
    }
    __syncthreads();

    int wid  = tid >> 5;
    int lane = tid & 31;
    int warpRow = wid * 32;
    unsigned sXb = sptr(sX);
    unsigned sWb = sptr(sWt);

    float acc[2][8][4];
    #pragma unroll
    for (int mt = 0; mt < 2; mt++)
        #pragma unroll
        for (int nt = 0; nt < 8; nt++)
            #pragma unroll
            for (int q = 0; q < 4; q++) acc[mt][nt][q] = 0.f;

    int sel = lane >> 3;
    int lr  = lane & 7;
    #pragma unroll
    for (int ks = 0; ks < 4; ks++){
        unsigned a[2][4];
        #pragma unroll
        for (int mt = 0; mt < 2; mt++){
            int rowl = warpRow + mt*16 + lr + ((sel & 1) << 3);
            int kb   = ks*32 + ((sel >> 1) << 4);
            ldm_x4(sXb + SW(rowl*128 + kb), a[mt][0], a[mt][1], a[mt][2], a[mt][3]);
        }
        #pragma unroll
        for (int j = 0; j < 4; j++){
            int kr = ks*16 + lr + ((sel & 1) << 3);
            int nb = j*32 + ((sel >> 1) << 4);
            unsigned b0, b1, b2, b3;
            ldm_x4t(sWb + SW(kr*128 + nb), b0, b1, b2, b3);
            mma16816(acc[0][2*j],   a[0], b0, b1);
            mma16816(acc[1][2*j],   a[1], b0, b1);
            mma16816(acc[0][2*j+1], a[0], b2, b3);
            mma16816(acc[1][2*j+1], a[1], b2, b3);
        }
    }

    int g  = lane >> 2;
    int i4 = lane & 3;
    int i2 = i4 * 2;
    #pragma unroll
    for (int nt = 0; nt < 8; nt++){
        float b0f = sBias[nt*8 + i2];
        float b1f = sBias[nt*8 + i2 + 1];
        float s0 = 0.f, s1 = 0.f, q0 = 0.f, q1 = 0.f;
        #pragma unroll
        for (int mt = 0; mt < 2; mt++){
            int row0 = rowBase + warpRow + mt*16 + g;
            float d0 = acc[mt][nt][0] + b0f;
            float d1 = acc[mt][nt][1] + b1f;
            float d2 = acc[mt][nt][2] + b0f;
            float d3 = acc[mt][nt][3] + b1f;
            if (row0 < Nn){
                __half2 hv = __float22half2_rn(make_float2(d0, d1));
                Y[row0*32 + nt*4 + i4] = *(unsigned*)&hv;
                s0 += d0; s1 += d1; q0 += d0*d0; q1 += d1*d1;
            }
            if (row0 + 8 < Nn){
                __half2 hv = __float22half2_rn(make_float2(d2, d3));
                Y[(row0+8)*32 + nt*4 + i4] = *(unsigned*)&hv;
                s0 += d2; s1 += d3; q0 += d2*d2; q1 += d3*d3;
            }
        }
        #pragma unroll
        for (int off = 4; off < 32; off <<= 1){
            s0 += __shfl_xor_sync(0xffffffffu, s0, off);
            s1 += __shfl_xor_sync(0xffffffffu, s1, off);
            q0 += __shfl_xor_sync(0xffffffffu, q0, off);
            q1 += __shfl_xor_sync(0xffffffffu, q1, off);
        }
        if (lane < 4){
            atomicAdd(&sSum[nt*8 + lane*2],     s0);
            atomicAdd(&sSum[nt*8 + lane*2 + 1], s1);
            atomicAdd(&sSsq[nt*8 + lane*2],     q0);
            atomicAdd(&sSsq[nt*8 + lane*2 + 1], q1);
        }
    }
    __syncthreads();
    if (tid < 64){
        atomicAdd(&statsOut[tid],    sSum[tid]);
        atomicAdd(&statsOut[64+tid], sSsq[tid]);
    }
}

// ---------------- final-layer pooling (BN+relu fused), fp16 source (R13 proven) ----------------
__global__ void k_pool(const __half* __restrict__ Uh, const int* __restrict__ gid,
                       float* __restrict__ pooled,
                       const float* __restrict__ statsIn,
                       const float* __restrict__ gamma,
                       const float* __restrict__ beta)
{
    __shared__ float sA[64], sB[64];
    int tid = threadIdx.x;
    bn_coeffs(statsIn, gamma, beta, sA, sB, tid);
    __syncthreads();
    int col  = tid & 63;
    int rl   = tid >> 6;
    int base = blockIdx.x * 128 + rl*32;
    float a = sA[col], b = sB[col];
    float acc = 0.f; int cur = -1;
    for (int j = 0; j < 32; j++){
        int r = base + j;
        if (r >= Nn) break;
        float x = __half2float(Uh[r*64 + col]);
        x = fmaxf(fmaf(x, a, b), 0.f);
        int g = gid[r];
        if (g != cur){
            if (cur >= 0) atomicAdd(&pooled[cur*64 + col], acc);
            cur = g; acc = x;
        } else {
            acc += x;
        }
    }
    if (cur >= 0) atomicAdd(&pooled[cur*64 + col], acc);
}

// ---------------- score = sum_i pooled_i @ Wp_i + bp_i (R13 proven) ----------------
__global__ void k_score(const float* __restrict__ Wp, const float* __restrict__ bp,
                        float* __restrict__ out)
{
    int t = blockIdx.x*blockDim.x + threadIdx.x;
    if (t >= NG*16) return;
    int g = t >> 4, o = t & 15;
    float acc = 0.f;
    #pragma unroll
    for (int i = 0; i < NPRED; i++){
        const float* __restrict__ P  = &g_pooled[(i*NG + g)*64];
        const float* __restrict__ Wr = Wp + i*64*16 + o;
        float s = 0.f;
        #pragma unroll 16
        for (int k = 0; k < 64; k++) s = fmaf(P[k], Wr[k*16], s);
        acc += s + bp[i*16 + o];
    }
    out[t] = acc;
}

// ---------------- launch ----------------
extern "C" void kernel_launch(void* const* d_in, const int* in_sizes, int n_in,
                              void* d_out, int out_size)
{
    const float* h    = (const float*)d_in[0];
    const int*   esrc = (const int*)  d_in[1];
    const int*   edst = (const int*)  d_in[2];
    const int*   gid  = (const int*)  d_in[3];
    const float* eps  = (const float*)d_in[4];
    const float* W1   = (const float*)d_in[5];
    const float* b1   = (const float*)d_in[6];
    const float* g1   = (const float*)d_in[7];
    const float* be1  = (const float*)d_in[8];
    const float* W2   = (const float*)d_in[9];
    const float* b2   = (const float*)d_in[10];
    const float* g2   = (const float*)d_in[11];
    const float* be2  = (const float*)d_in[12];
    const float* Wp   = (const float*)d_in[13];
    const float* bp   = (const float*)d_in[14];
    float* out = (float*)d_out;

    void *p_pooled, *p_pre16, *p_t16, *p_u16, *p_h16, *p_stats;
    cudaGetSymbolAddress(&p_pooled, g_pooled);
    cudaGetSymbolAddress(&p_pre16,  g_pre16);
    cudaGetSymbolAddress(&p_t16,    g_t16);
    cudaGetSymbolAddress(&p_u16,    g_u16);
    cudaGetSymbolAddress(&p_h16,    g_h16);
    cudaGetSymbolAddress(&p_stats,  g_stats);
    float* stats  = (float*)p_stats;
    float* pooled = (float*)p_pooled;

    // CSR by destination: hist(+rank+convert), fused scan, atomic-free scatter
    k_hist<<<(Ee+255)/256, 256>>>(edst, h);
    int nb = (Nn + 1023)/1024;
    k_scan<<<nb, 1024>>>(nb);
    k_scatter<<<(Ee+255)/256, 256>>>(esrc, edst);

    int gemmB_ = (Nn + 255)/256;
    int aggB   = Nn/16;

    for (int i = 0; i < NGIN; i++){
        float* s1 = stats + (2*i)*128;
        float* s2 = stats + (2*i+1)*128;

        if (i == 0)
            k_agg<0><<<aggB, 256>>>((const uint2*)p_h16, eps, 0, gid, pooled,
                                    nullptr, nullptr, nullptr);
        else
            k_agg<1><<<aggB, 256>>>((const uint2*)p_u16, eps, i, gid,
                                    pooled + (size_t)i*NG*Dd,
                                    stats + (2*(i-1)+1)*128,
                                    g2 + (i-1)*64, be2 + (i-1)*64);

        k_gemm<0><<<gemmB_, 256>>>((const uint4*)p_pre16, W1 + i*4096, b1 + i*64,
                                   (unsigned*)p_t16, nullptr, s1, nullptr, nullptr);
        k_gemm<1><<<gemmB_, 256>>>((const uint4*)p_t16, W2 + i*4096, b2 + i*64,
                                   (unsigned*)p_u16, s1, s2, g1 + i*64, be1 + i*64);
    }

    k_pool<<<(Nn + 127)/128, 256>>>((const __half*)p_u16, gid,
                                    pooled + (size_t)NGIN*NG*Dd,
                                    stats + 7*128, g2 + 3*64, be2 + 3*64);

    k_score<<<(NG*16 + 255)/256, 256>>>(Wp, bp, out);
}